// round 4
// baseline (speedup 1.0000x reference)
#include <cuda_runtime.h>
#include <cstdint>

// Problem constants
constexpr int Bc = 2, Sc = 2048, Dc = 1024, Hc = 16;
constexpr int Mc = Bc * Sc;        // 4096
constexpr int NQKV = 3 * Dc;       // 3072

// Scratch (device globals; no allocation allowed)
__device__ uint32_t g_qkv[Mc * NQKV];    // QKV output, tf32 bits, plain layout
__device__ float    g_ctx[Mc * Dc];      // context (fp32, feeds out-proj)
__device__ uint32_t g_qpack[Mc * Dc];    // query, tf32 bits, pair-packed along K
__device__ uint32_t g_wqkv[Dc * NQKV];   // w_qkv tf32 bits plain
__device__ uint32_t g_wfc[Dc * Dc];      // w_fc  tf32 bits plain

// ---------------------------------------------------------------------------
// helpers
// ---------------------------------------------------------------------------
__device__ __forceinline__ uint32_t f2tf32(float f) {
    uint32_t u;
    asm("cvt.rna.tf32.f32 %0, %1;" : "=r"(u) : "f"(f));
    return u;
}

__device__ __forceinline__ void mma_tf32(float* c, const uint32_t* a, const uint32_t* b) {
    asm volatile(
        "mma.sync.aligned.m16n8k8.row.col.f32.tf32.tf32.f32 "
        "{%0,%1,%2,%3}, {%4,%5,%6,%7}, {%8,%9}, {%0,%1,%2,%3};\n"
        : "+f"(c[0]), "+f"(c[1]), "+f"(c[2]), "+f"(c[3])
        : "r"(a[0]), "r"(a[1]), "r"(a[2]), "r"(a[3]), "r"(b[0]), "r"(b[1]));
}

__device__ __forceinline__ void cp16(void* smem, const void* gmem) {
    uint32_t s = (uint32_t)__cvta_generic_to_shared(smem);
    asm volatile("cp.async.ca.shared.global [%0], [%1], 16;" :: "r"(s), "l"(gmem));
}
__device__ __forceinline__ void cp_commit() { asm volatile("cp.async.commit_group;"); }
__device__ __forceinline__ void cp_wait1()  { asm volatile("cp.async.wait_group 1;"); }

// ---------------------------------------------------------------------------
// Prepack kernels (run once per launch; tiny)
// ---------------------------------------------------------------------------
__global__ __launch_bounds__(256) void cvt_tf32_kernel(
    const float4* __restrict__ in, uint4* __restrict__ out, int n4)
{
    int i = blockIdx.x * 256 + threadIdx.x;
    if (i < n4) {
        float4 v = in[i];
        out[i] = make_uint4(f2tf32(v.x), f2tf32(v.y), f2tf32(v.z), f2tf32(v.w));
    }
}

// pair-pack along last dim (groups of 8): slot(d) = (d&~7) + 2*(d&3) + ((d>>2)&1)
__global__ __launch_bounds__(256) void pack_tf32_kernel(
    const float4* __restrict__ in, uint32_t* __restrict__ out, int n4)
{
    int i = blockIdx.x * 256 + threadIdx.x;
    if (i < n4) {
        float4 v = in[i];
        int e  = i * 4;
        int g8 = e & ~7;
        int p  = (e >> 2) & 1;
        out[g8 + 0 + p] = f2tf32(v.x);
        out[g8 + 2 + p] = f2tf32(v.y);
        out[g8 + 4 + p] = f2tf32(v.z);
        out[g8 + 6 + p] = f2tf32(v.w);
    }
}

// ---------------------------------------------------------------------------
// Tensor-core GEMM + bias, 2-stage cp.async pipeline.
// BM=256, BN=64, BK=32. 256 threads = 8 warps (4x2), warp tile 64x32.
// APACK: A is tf32-bit, pair-packed  -> A frags via LDS.64, no CVT.
// else : A is fp32                   -> cvt at frag load.
// W always tf32 bits, plain layout   -> B frags via 2x LDS.32, no CVT.
// OUTTF: store C as tf32 bits (uint32), else fp32.
// ---------------------------------------------------------------------------
constexpr int GA_STR  = 36;   // unpacked A floats per row
constexpr int AP_STR2 = 20;   // packed A uint2 per row (20 % 16 == 4 -> cf)
constexpr int GW_STR  = 72;   // W uint32 per row
constexpr int GEMM_SMEM_UNPACK = (2 * 256 * GA_STR + 2 * 32 * GW_STR) * 4;   // 92160
constexpr int GEMM_SMEM_PACK   = 2 * 256 * AP_STR2 * 8 + 2 * 32 * GW_STR * 4; // 100352

template<bool APACK, bool OUTTF>
__global__ __launch_bounds__(256) void gemm_tc(
    const void* __restrict__ Av, const uint32_t* __restrict__ W,
    const float* __restrict__ bias, void* __restrict__ Cv,
    int M, int N, int K)
{
    extern __shared__ __align__(16) char gsmc[];

    const int tid    = threadIdx.x;
    const int warp   = tid >> 5;
    const int lane   = tid & 31;
    const int gid    = lane >> 2;
    const int tig    = lane & 3;
    const int warp_m = warp >> 1;
    const int warp_n = warp & 1;
    const int m0 = blockIdx.y * 256;
    const int n0 = blockIdx.x * 64;
    const int mw = warp_m * 64;
    const int nw = warp_n * 32;

    // smem partitions
    uint2*    Ap = (uint2*)gsmc;                                   // [2][256][AP_STR2]
    float*    Af = (float*)gsmc;                                   // [2][256][GA_STR]
    uint32_t* Ws = APACK ? (uint32_t*)(gsmc + 2 * 256 * AP_STR2 * 8)
                         : (uint32_t*)(gsmc + 2 * 256 * GA_STR * 4); // [2][32][GW_STR]

    auto load_stage = [&](int s, int kb) {
        if (APACK) {
            const uint32_t* A = (const uint32_t*)Av;
            char* asb = gsmc + (size_t)s * 256 * AP_STR2 * 8;
#pragma unroll
            for (int j = 0; j < 8; j++) {
                int id    = tid + j * 256;
                int row   = id >> 3;
                int chunk = id & 7;
                cp16(asb + (size_t)row * AP_STR2 * 8 + chunk * 16,
                     A + (size_t)(m0 + row) * K + kb + chunk * 4);
            }
        } else {
            const float* A = (const float*)Av;
            char* asb = gsmc + (size_t)s * 256 * GA_STR * 4;
#pragma unroll
            for (int j = 0; j < 8; j++) {
                int id   = tid + j * 256;
                int row  = id >> 3;
                int colq = (id & 7) * 4;
                cp16(asb + (size_t)row * GA_STR * 4 + colq * 4,
                     A + (size_t)(m0 + row) * K + kb + colq);
            }
        }
        {
            char* wsb = (char*)(Ws + (size_t)s * 32 * GW_STR);
#pragma unroll
            for (int j = 0; j < 2; j++) {
                int id  = tid + j * 256;
                int row = id >> 4;
                int c4  = (id & 15) * 4;
                cp16(wsb + (size_t)row * GW_STR * 4 + c4 * 4,
                     W + (size_t)(kb + row) * N + n0 + c4);
            }
        }
    };

    float acc[4][4][4];
#pragma unroll
    for (int i = 0; i < 4; i++)
#pragma unroll
        for (int j = 0; j < 4; j++)
#pragma unroll
            for (int q = 0; q < 4; q++) acc[i][j][q] = 0.f;

    const int nK = K / 32;
    load_stage(0, 0);
    cp_commit();

    for (int kbi = 0; kbi < nK; kbi++) {
        const int s = kbi & 1;
        if (kbi + 1 < nK) load_stage(s ^ 1, (kbi + 1) * 32);
        cp_commit();
        cp_wait1();
        __syncthreads();

        const uint2*    ap = Ap + (size_t)s * 256 * AP_STR2;
        const float*    af_s = Af + (size_t)s * 256 * GA_STR;
        const uint32_t* ws = Ws + (size_t)s * 32 * GW_STR;

#pragma unroll
        for (int kk = 0; kk < 4; kk++) {
            const int k8 = kk * 8;
            uint32_t af[4][4];
            if (APACK) {
#pragma unroll
                for (int mt = 0; mt < 4; mt++) {
                    int r = mw + mt * 16 + gid;
                    uint2 lo = ap[(size_t)r * AP_STR2 + kk * 4 + tig];
                    uint2 hi = ap[(size_t)(r + 8) * AP_STR2 + kk * 4 + tig];
                    af[mt][0] = lo.x; af[mt][1] = hi.x;
                    af[mt][2] = lo.y; af[mt][3] = hi.y;
                }
            } else {
#pragma unroll
                for (int mt = 0; mt < 4; mt++) {
                    int r = mw + mt * 16 + gid;
                    af[mt][0] = f2tf32(af_s[r * GA_STR + k8 + tig]);
                    af[mt][1] = f2tf32(af_s[(r + 8) * GA_STR + k8 + tig]);
                    af[mt][2] = f2tf32(af_s[r * GA_STR + k8 + tig + 4]);
                    af[mt][3] = f2tf32(af_s[(r + 8) * GA_STR + k8 + tig + 4]);
                }
            }
#pragma unroll
            for (int nt = 0; nt < 4; nt++) {
                uint32_t bf[2];
                int c = nw + nt * 8 + gid;
                bf[0] = ws[(k8 + tig) * GW_STR + c];
                bf[1] = ws[(k8 + tig + 4) * GW_STR + c];
#pragma unroll
                for (int mt = 0; mt < 4; mt++)
                    mma_tf32(acc[mt][nt], af[mt], bf);
            }
        }
        __syncthreads();
    }

#pragma unroll
    for (int nt = 0; nt < 4; nt++) {
        int c = n0 + nw + nt * 8 + 2 * tig;
        float b0 = bias[c], b1 = bias[c + 1];
#pragma unroll
        for (int mt = 0; mt < 4; mt++) {
            int r = m0 + mw + mt * 16 + gid;
            if (OUTTF) {
                uint32_t* C = (uint32_t*)Cv;
                *(uint2*)(C + (size_t)r * N + c) =
                    make_uint2(f2tf32(acc[mt][nt][0] + b0), f2tf32(acc[mt][nt][1] + b1));
                *(uint2*)(C + (size_t)(r + 8) * N + c) =
                    make_uint2(f2tf32(acc[mt][nt][2] + b0), f2tf32(acc[mt][nt][3] + b1));
            } else {
                float* C = (float*)Cv;
                *(float2*)(C + (size_t)r * N + c) =
                    make_float2(acc[mt][nt][0] + b0, acc[mt][nt][1] + b1);
                *(float2*)(C + (size_t)(r + 8) * N + c) =
                    make_float2(acc[mt][nt][2] + b0, acc[mt][nt][3] + b1);
            }
        }
    }
}

// ---------------------------------------------------------------------------
// Fused attention (recompute strategy), tf32-bit qkv input.
// Block = (b, h, 128-row q tile), 256 threads = 8 warps, warp = 16 q-rows.
// K staged pair-packed along d (LDS.64 B-frags, no CVT).
// V staged pair-packed along k (LDS.64 B-frags, no CVT).
// ---------------------------------------------------------------------------
constexpr int QSTR    = 68;    // probs (f32) / Q (u32) row stride
constexpr int KP_STR2 = 36;    // Kp row stride in uint2 (36 % 16 == 4 -> cf)
constexpr int VP_STR2 = 72;    // Vp row stride in uint2 (72 % 16 == 8 -> cf)

constexpr int SM_PROBS_W = 128 * QSTR;      // 8704 words
constexpr int SM_KP2     = 64 * KP_STR2;    // 2304 uint2
constexpr int SM_VP2     = 32 * VP_STR2;    // 2304 uint2
constexpr int ATTN_SMEM_BYTES = SM_PROBS_W * 4 + SM_KP2 * 8 + SM_VP2 * 8;  // 71680

__global__ __launch_bounds__(256, 2) void attn_tc_kernel(
    const uint32_t* __restrict__ qkv, const float* __restrict__ mask,
    float* __restrict__ ctx_out, float* __restrict__ attn_out)
{
    extern __shared__ __align__(16) char smc[];
    float*    probs  = (float*)smc;                         // [128][QSTR]
    uint32_t* Qu     = (uint32_t*)smc;                      // aliases probs
    uint32_t* Kp_u32 = (uint32_t*)(smc + SM_PROBS_W * 4);   // [64][KP_STR2] as u32 pairs
    uint2*    Kp2    = (uint2*)Kp_u32;
    uint32_t* Vp_u32 = Kp_u32 + SM_KP2 * 2;                 // [32][VP_STR2]
    uint2*    Vp2    = (uint2*)Vp_u32;

    const int tid  = threadIdx.x;
    const int warp = tid >> 5;
    const int lane = tid & 31;
    const int gid  = lane >> 2;
    const int tig  = lane & 3;
    const int mw   = warp * 16;
    const int q0   = blockIdx.x * 128;
    const int h    = blockIdx.y;
    const int b    = blockIdx.z;

    const uint32_t* qb = qkv + (size_t)b * Sc * NQKV + h * 64;          // Q section
    const uint32_t* kb_ptr = qb + Dc;                                   // K section
    const uint32_t* vb_ptr = qb + 2 * Dc;                               // V section
    const float* mrow0 = mask + (size_t)b * Sc * Sc + (size_t)(q0 + mw + gid) * Sc;
    const float* mrow1 = mrow0 + 8 * Sc;

    // ---- stage Q tile [128 x 64] (raw tf32 bits), extract A fragments ----
#pragma unroll
    for (int j = 0; j < 8; j++) {
        int id   = tid + j * 256;
        int row  = id >> 4;
        int colq = (id & 15) * 4;
        uint4 v = *(const uint4*)(qb + (size_t)(q0 + row) * NQKV + colq);
        *(uint4*)&Qu[row * QSTR + colq] = v;
    }
    __syncthreads();

    uint32_t aq[8][4];
#pragma unroll
    for (int kk = 0; kk < 8; kk++) {
        int d = kk * 8 + tig;
        aq[kk][0] = Qu[(mw + gid) * QSTR + d];
        aq[kk][1] = Qu[(mw + gid + 8) * QSTR + d];
        aq[kk][2] = Qu[(mw + gid) * QSTR + d + 4];
        aq[kk][3] = Qu[(mw + gid + 8) * QSTR + d + 4];
    }
    __syncthreads();   // Qu free -> probs in pass B

    // K stage helper: pair-pack along d. slot(d) = 2*((d>>3)*4 + (d&3)) + ((d>>2)&1)
    auto stage_K = [&](int kb) {
#pragma unroll
        for (int j = 0; j < 4; j++) {
            int id   = tid + j * 256;
            int row  = id >> 4;
            int colq = (id & 15) * 4;
            uint4 v = *(const uint4*)(kb_ptr + (size_t)(kb + row) * NQKV + colq);
            int base = row * (KP_STR2 * 2) + (colq >> 3) * 8 + ((colq >> 2) & 1);
            Kp_u32[base + 0] = v.x;
            Kp_u32[base + 2] = v.y;
            Kp_u32[base + 4] = v.z;
            Kp_u32[base + 6] = v.w;
        }
    };

    // ---- Pass A: online (m, l) ----
    float m0 = -3.0e38f, m1 = -3.0e38f, l0 = 0.f, l1 = 0.f;

    for (int kb = 0; kb < Sc; kb += 64) {
        __syncthreads();
        stage_K(kb);
        __syncthreads();

#pragma unroll
        for (int nt = 0; nt < 8; nt++) {
            float s[4] = {0.f, 0.f, 0.f, 0.f};
            const uint2* krow = Kp2 + (nt * 8 + gid) * KP_STR2;
#pragma unroll
            for (int kk = 0; kk < 8; kk++) {
                uint2 bb = krow[kk * 4 + tig];
                mma_tf32(s, aq[kk], (const uint32_t*)&bb);
            }
            int c = kb + nt * 8 + 2 * tig;
            float2 mk0 = *(const float2*)(mrow0 + c);
            float2 mk1 = *(const float2*)(mrow1 + c);
            float s0 = s[0] * 0.125f + mk0.x;
            float s1 = s[1] * 0.125f + mk0.y;
            float s2 = s[2] * 0.125f + mk1.x;
            float s3 = s[3] * 0.125f + mk1.y;

            float mn0 = fmaxf(m0, fmaxf(s0, s1));
            if (mn0 != m0) l0 *= __expf(m0 - mn0);
            l0 += __expf(s0 - mn0) + __expf(s1 - mn0);
            m0 = mn0;

            float mn1 = fmaxf(m1, fmaxf(s2, s3));
            if (mn1 != m1) l1 *= __expf(m1 - mn1);
            l1 += __expf(s2 - mn1) + __expf(s3 - mn1);
            m1 = mn1;
        }
    }

    // combine (m,l) across the 4 tig lanes of each row
#pragma unroll
    for (int off = 1; off < 4; off <<= 1) {
        float mo = __shfl_xor_sync(0xffffffffu, m0, off, 4);
        float lo = __shfl_xor_sync(0xffffffffu, l0, off, 4);
        float mn = fmaxf(m0, mo);
        l0 = l0 * __expf(m0 - mn) + lo * __expf(mo - mn);
        m0 = mn;
        mo = __shfl_xor_sync(0xffffffffu, m1, off, 4);
        lo = __shfl_xor_sync(0xffffffffu, l1, off, 4);
        mn = fmaxf(m1, mo);
        l1 = l1 * __expf(m1 - mn) + lo * __expf(mo - mn);
        m1 = mn;
    }
    const float iz0 = 1.f / l0;
    const float iz1 = 1.f / l1;

    // ---- Pass B: recompute, normalize, PV, stream attn_prob ----
    float ctx[8][4];
#pragma unroll
    for (int dt = 0; dt < 8; dt++)
#pragma unroll
        for (int q = 0; q < 4; q++) ctx[dt][q] = 0.f;

    float* aout = attn_out + ((size_t)(b * Hc + h) * Sc + q0) * Sc;

    for (int kb = 0; kb < Sc; kb += 64) {
        __syncthreads();
        stage_K(kb);
        // V stage: pair-pack along k rows. row r -> slotrow kk*4+(u&3), comp u>>2
#pragma unroll
        for (int j = 0; j < 4; j++) {
            int id   = tid + j * 256;
            int row  = id >> 4;
            int colq = (id & 15) * 4;
            uint4 v = *(const uint4*)(vb_ptr + (size_t)(kb + row) * NQKV + colq);
            int u    = row & 7;
            int base = ((row >> 3) * 4 + (u & 3)) * (VP_STR2 * 2) + colq * 2 + (u >> 2);
            Vp_u32[base + 0] = v.x;
            Vp_u32[base + 2] = v.y;
            Vp_u32[base + 4] = v.z;
            Vp_u32[base + 6] = v.w;
        }
        __syncthreads();

        // QK recompute + probs write (own 16 rows)
#pragma unroll
        for (int nt = 0; nt < 8; nt++) {
            float s[4] = {0.f, 0.f, 0.f, 0.f};
            const uint2* krow = Kp2 + (nt * 8 + gid) * KP_STR2;
#pragma unroll
            for (int kk = 0; kk < 8; kk++) {
                uint2 bb = krow[kk * 4 + tig];
                mma_tf32(s, aq[kk], (const uint32_t*)&bb);
            }
            int cl = nt * 8 + 2 * tig;
            int c  = kb + cl;
            float2 mk0 = *(const float2*)(mrow0 + c);
            float2 mk1 = *(const float2*)(mrow1 + c);
            float p0 = __expf(s[0] * 0.125f + mk0.x - m0) * iz0;
            float p1 = __expf(s[1] * 0.125f + mk0.y - m0) * iz0;
            float p2 = __expf(s[2] * 0.125f + mk1.x - m1) * iz1;
            float p3 = __expf(s[3] * 0.125f + mk1.y - m1) * iz1;
            *(float2*)&probs[(mw + gid) * QSTR + cl]     = make_float2(p0, p1);
            *(float2*)&probs[(mw + gid + 8) * QSTR + cl] = make_float2(p2, p3);
        }
        __syncthreads();

        // PV: ctx += P(16 x 64) @ V(64 x 64), own 16 rows
#pragma unroll
        for (int kk = 0; kk < 8; kk++) {
            uint32_t ap[4];
            int kt = kk * 8 + tig;
            ap[0] = f2tf32(probs[(mw + gid) * QSTR + kt]);
            ap[1] = f2tf32(probs[(mw + gid + 8) * QSTR + kt]);
            ap[2] = f2tf32(probs[(mw + gid) * QSTR + kt + 4]);
            ap[3] = f2tf32(probs[(mw + gid + 8) * QSTR + kt + 4]);
            const uint2* vrow = Vp2 + (kk * 4 + tig) * VP_STR2;
#pragma unroll
            for (int dt = 0; dt < 8; dt++) {
                uint2 bb = vrow[dt * 8 + gid];
                mma_tf32(ctx[dt], ap, (const uint32_t*)&bb);
            }
        }

        // stream normalized probs chunk to global (coalesced float4)
#pragma unroll
        for (int j = 0; j < 8; j++) {
            int id   = tid + j * 256;
            int row  = id >> 4;
            int colq = (id & 15) * 4;
            float4 p4 = *(float4*)&probs[row * QSTR + colq];
            *(float4*)(aout + (size_t)row * Sc + kb + colq) = p4;
        }
    }

    // ---- context write (fp32) ----
#pragma unroll
    for (int dt = 0; dt < 8; dt++) {
        int d = dt * 8 + 2 * tig;
        int r = q0 + mw + gid;
        *(float2*)(ctx_out + (size_t)(b * Sc + r) * Dc + h * 64 + d) =
            make_float2(ctx[dt][0], ctx[dt][1]);
        *(float2*)(ctx_out + (size_t)(b * Sc + r + 8) * Dc + h * 64 + d) =
            make_float2(ctx[dt][2], ctx[dt][3]);
    }
}

// ---------------------------------------------------------------------------
extern "C" void kernel_launch(void* const* d_in, const int* in_sizes, int n_in,
                              void* d_out, int out_size)
{
    const float* query = (const float*)d_in[0];
    const float* mask  = (const float*)d_in[1];
    const float* w_qkv = (const float*)d_in[2];
    const float* b_qkv = (const float*)d_in[3];
    const float* w_fc  = (const float*)d_in[4];
    const float* b_fc  = (const float*)d_in[5];

    float* out      = (float*)d_out;
    float* ctx_out  = out;                         // [2,2048,1024]
    float* attn_out = out + (size_t)Mc * Dc;       // [2,16,2048,2048]

    uint32_t *qkv_ptr = nullptr, *qpack_ptr = nullptr, *wqkv_ptr = nullptr, *wfc_ptr = nullptr;
    float* ctx_ptr = nullptr;
    cudaGetSymbolAddress((void**)&qkv_ptr, g_qkv);
    cudaGetSymbolAddress((void**)&ctx_ptr, g_ctx);
    cudaGetSymbolAddress((void**)&qpack_ptr, g_qpack);
    cudaGetSymbolAddress((void**)&wqkv_ptr, g_wqkv);
    cudaGetSymbolAddress((void**)&wfc_ptr, g_wfc);

    cudaFuncSetAttribute((const void*)gemm_tc<true, true>,
                         cudaFuncAttributeMaxDynamicSharedMemorySize, GEMM_SMEM_PACK);
    cudaFuncSetAttribute((const void*)gemm_tc<false, false>,
                         cudaFuncAttributeMaxDynamicSharedMemorySize, GEMM_SMEM_UNPACK);
    cudaFuncSetAttribute((const void*)attn_tc_kernel,
                         cudaFuncAttributeMaxDynamicSharedMemorySize, ATTN_SMEM_BYTES);

    // 0) prepack: query -> packed tf32, weights -> plain tf32
    {
        int n4q = Mc * Dc / 4;
        pack_tf32_kernel<<<(n4q + 255) / 256, 256>>>((const float4*)query, qpack_ptr, n4q);
        int n4w = Dc * NQKV / 4;
        cvt_tf32_kernel<<<(n4w + 255) / 256, 256>>>((const float4*)w_qkv, (uint4*)wqkv_ptr, n4w);
        int n4f = Dc * Dc / 4;
        cvt_tf32_kernel<<<(n4f + 255) / 256, 256>>>((const float4*)w_fc, (uint4*)wfc_ptr, n4f);
    }
    // 1) QKV projection (packed A, tf32 W, tf32-bit output)
    {
        dim3 grid(NQKV / 64, Mc / 256);
        gemm_tc<true, true><<<grid, 256, GEMM_SMEM_PACK>>>(
            qpack_ptr, wqkv_ptr, b_qkv, qkv_ptr, Mc, NQKV, Dc);
    }
    // 2) Fused attention
    {
        dim3 grid(Sc / 128, Hc, Bc);
        attn_tc_kernel<<<grid, 256, ATTN_SMEM_BYTES>>>(qkv_ptr, mask, ctx_ptr, attn_out);
    }
    // 3) Output projection (fp32 A, tf32 W, fp32 output)
    {
        dim3 grid(Dc / 64, Mc / 256);
        gemm_tc<false, false><<<grid, 256, GEMM_SMEM_UNPACK>>>(
            ctx_ptr, wfc_ptr, b_fc, ctx_out, Mc, Dc, Dc);
    }
}